// round 11
// baseline (speedup 1.0000x reference)
#include <cuda_runtime.h>
#include <cuda_bf16.h>
#include <math.h>

#define N_PL 16
#define OBJ  10
#define MOBJ 36
#define RPB  16    // rows (warps) per block
#define STR  12    // padded row stride for 10x10 matrices (48B, 16B-aligned)

// Compile-time pair tables (static .global data; coalesced LDG per warp).
// pairA[l] = (j,k) of 55-pair l  and (j,k) of 55-pair 32+l (lanes 0-22; dc after)
__device__ const uchar4 g_pairA[32] = {
    {0,0,3,8},{0,1,3,9},{0,2,4,4},{0,3,4,5},{0,4,4,6},{0,5,4,7},{0,6,4,8},{0,7,4,9},
    {0,8,5,5},{0,9,5,6},{1,1,5,7},{1,2,5,8},{1,3,5,9},{1,4,6,6},{1,5,6,7},{1,6,6,8},
    {1,7,6,9},{1,8,7,7},{1,9,7,8},{2,2,7,9},{2,3,8,8},{2,4,8,9},{2,5,9,9},{2,6,9,9},
    {2,7,9,9},{2,8,9,9},{2,9,9,9},{3,3,9,9},{3,4,9,9},{3,5,9,9},{3,6,9,9},{3,7,9,9}};
// pairB[l].xy = (j,k) of 45-pair l (block1); .zw = (j,k) of 45-pair 32+(l>>1) (block2 halves)
__device__ const uchar4 g_pairB[32] = {
    {0,1,4,7},{0,2,4,7},{0,3,4,8},{0,4,4,8},{0,5,4,9},{0,6,4,9},{0,7,5,6},{0,8,5,6},
    {0,9,5,7},{1,2,5,7},{1,3,5,8},{1,4,5,8},{1,5,5,9},{1,6,5,9},{1,7,6,7},{1,8,6,7},
    {1,9,6,8},{2,3,6,8},{2,4,6,9},{2,5,6,9},{2,6,7,8},{2,7,7,8},{2,8,7,9},{2,9,7,9},
    {3,4,8,9},{3,5,8,9},{3,6,8,9},{3,7,8,9},{3,8,8,9},{3,9,8,9},{4,5,8,9},{4,6,8,9}};

// plin on pre-scaled argument y = 16*x, y in [0,16]; plin = A[i] + y*B[i], i=(int)y
__device__ __forceinline__ float plin2(const float2* __restrict__ tb, float y) {
    int i = (int)y;
    float2 p = tb[i];
    return fmaf(y, p.y, p.x);
}

// product of 10 plin(1-|colj[i]-colk[i]|) + att term, vectorized loads
__device__ __forceinline__ float simprod(const float* __restrict__ ddT,
                                         const float2* __restrict__ tb2,
                                         int j, int k, float a4j, float a4k) {
    const float4* cj = (const float4*)(ddT + j * STR);
    const float4* ck = (const float4*)(ddT + k * STR);
    float4 a0 = cj[0], b0 = ck[0];
    float4 a1 = cj[1], b1 = ck[1];
    float2 a2 = *(const float2*)(ddT + j * STR + 8);
    float2 b2 = *(const float2*)(ddT + k * STR + 8);
    float t0 = plin2(tb2, fmaf(fabsf(a0.x - b0.x), -16.0f, 16.0f));
    float t1 = plin2(tb2, fmaf(fabsf(a0.y - b0.y), -16.0f, 16.0f));
    float t2 = plin2(tb2, fmaf(fabsf(a0.z - b0.z), -16.0f, 16.0f));
    float t3 = plin2(tb2, fmaf(fabsf(a0.w - b0.w), -16.0f, 16.0f));
    float t4 = plin2(tb2, fmaf(fabsf(a1.x - b1.x), -16.0f, 16.0f));
    float t5 = plin2(tb2, fmaf(fabsf(a1.y - b1.y), -16.0f, 16.0f));
    float t6 = plin2(tb2, fmaf(fabsf(a1.z - b1.z), -16.0f, 16.0f));
    float t7 = plin2(tb2, fmaf(fabsf(a1.w - b1.w), -16.0f, 16.0f));
    float t8 = plin2(tb2, fmaf(fabsf(a2.x - b2.x), -16.0f, 16.0f));
    float t9 = plin2(tb2, fmaf(fabsf(a2.y - b2.y), -16.0f, 16.0f));
    float ta = plin2(tb2, fmaf(fabsf(a4j - a4k), -4.0f, 16.0f));   // att stored x4
    float p0 = (t0 * t1) * (t2 * t3);
    float p1 = (t4 * t5) * (t6 * t7);
    float p2 = (t8 * t9) * ta;
    return (p0 * p1) * p2;
}

__global__ __launch_bounds__(512, 2)
void counter_kernel(const float* __restrict__ boxes,      // [n, 4, 36]
                    const float* __restrict__ attention,  // [n, 36]
                    const float* __restrict__ ws,         // [8, 17]
                    float* __restrict__ out,              // [n, 11]
                    int n) {
    __shared__ float4 tabRel[N_PL + 1];    // (A0,B0,A3,B3) keyed by yr
    __shared__ float4 tabDist[N_PL + 1];   // (A1,B1,A4,B4) keyed by yd
    __shared__ float2 tab2[N_PL + 1];
    __shared__ float2 tab5[N_PL + 1];
    __shared__ float2 tab6[N_PL + 1];      // keyed by yd (index reused)
    __shared__ float2 tab7[N_PL + 1];
    __shared__ uint4  karr[RPB][9];        // 36 sortable 32-bit keys per row
    __shared__ float  att[RPB][OBJ];       // holds 4*sigmoid
    __shared__ float4 boxs[RPB][OBJ];
    __shared__ float  ddT[RPB][OBJ * STR];
    __shared__ float  smP[RPB][OBJ * STR];
    __shared__ float  invr[RPB][OBJ];

    const int t = threadIdx.x;
    const int w = t >> 5, l = t & 31;
    const int row = blockIdx.x * RPB + w;
    const bool act = row < n;

    // ---- plin tables built by warps 0-7 only (amortized over 16 rows) ----
    if (w < 8) {
        float wv0 = (l <= N_PL) ? fabsf(ws[w * 17 + l]) : 0.0f;
        float cs = wv0;
        #pragma unroll
        for (int o = 1; o <= 16; o <<= 1) {
            float up = __shfl_up_sync(0xffffffffu, cs, o);
            if (l >= o) cs += up;
        }
        float totalw = __shfl_sync(0xffffffffu, cs, N_PL);
        float inv = __fdividef(1.0f, totalw);
        float wnext = __shfl_down_sync(0xffffffffu, wv0, 1);
        float B = (l < N_PL) ? wnext * inv : 0.0f;
        float A = fmaf(-(float)l, B, cs * inv);
        if (l <= N_PL) {
            if      (w == 0) { ((float*)tabRel)[4*l]   = A; ((float*)tabRel)[4*l+1]  = B; }
            else if (w == 3) { ((float*)tabRel)[4*l+2] = A; ((float*)tabRel)[4*l+3]  = B; }
            else if (w == 1) { ((float*)tabDist)[4*l]  = A; ((float*)tabDist)[4*l+1] = B; }
            else if (w == 4) { ((float*)tabDist)[4*l+2]= A; ((float*)tabDist)[4*l+3] = B; }
            else if (w == 2) tab2[l] = make_float2(A, B);
            else if (w == 5) tab5[l] = make_float2(A, B);
            else if (w == 6) tab6[l] = make_float2(A, B);
            else             tab7[l] = make_float2(A, B);
        }
    }

    // ---- load attention, build monotone 32-bit sortable keys (branchless) ----
    float v1 = 0.0f, v2 = 0.0f;
    if (act) {
        v1 = attention[(size_t)row * MOBJ + l];
        if (l < 4) v2 = attention[(size_t)row * MOBJ + 32 + l];
    }
    unsigned u1 = __float_as_uint(v1);
    unsigned kv1 = u1 ^ (unsigned)(((int)u1 >> 31) | 0x80000000);
    ((unsigned*)karr[w])[l] = kv1;
    unsigned u2 = __float_as_uint(v2);
    unsigned kv2 = u2 ^ (unsigned)(((int)u2 >> 31) | 0x80000000);
    if (l < 4) ((unsigned*)karr[w])[32 + l] = kv2;
    __syncthreads();   // the ONLY block barrier: tables (cross-warp) + own keys

    // ---- rank among all 36 via strict > (keys unique: continuous input data) ----
    int r1 = 0;
    const uint4* kp = karr[w];
    #pragma unroll
    for (int p = 0; p < 9; p++) {
        uint4 kk = kp[p];
        r1 += (kk.x > kv1) + (kk.y > kv1) + (kk.z > kv1) + (kk.w > kv1);
    }
    uint4 ex = kp[8];   // keys 32..35

    unsigned b0 = __ballot_sync(0xffffffffu, kv1 > ex.x);
    unsigned b1 = __ballot_sync(0xffffffffu, kv1 > ex.y);
    unsigned b2 = __ballot_sync(0xffffffffu, kv1 > ex.z);
    unsigned b3 = __ballot_sync(0xffffffffu, kv1 > ex.w);
    int r2 = (l == 0) ? __popc(b0) : (l == 1) ? __popc(b1) : (l == 2) ? __popc(b2) : __popc(b3);
    r2 += (ex.x > kv2) + (ex.y > kv2) + (ex.z > kv2) + (ex.w > kv2);

    // ---- gather selected objects (att stored as 4*sigmoid) ----
    if (act && r1 < OBJ) {
        att[w][r1] = __fdividef(4.0f, 1.0f + __expf(-v1));
        const float* bp = boxes + (size_t)row * (4 * MOBJ) + l;
        boxs[w][r1] = make_float4(bp[0], bp[MOBJ], bp[2 * MOBJ], bp[3 * MOBJ]);
    }
    if (act && l < 4 && r2 < OBJ) {
        att[w][r2] = __fdividef(4.0f, 1.0f + __expf(-v2));
        const float* bp = boxes + (size_t)row * (4 * MOBJ) + 32 + l;
        boxs[w][r2] = make_float4(bp[0], bp[MOBJ], bp[2 * MOBJ], bp[3 * MOBJ]);
    }
    __syncwarp();

    // ---- pairwise (55 pairs: lane l; lanes 0-22 also pair 32+l) ----
    const uchar4 pa = g_pairA[l];
    const float* aw = att[w];
    float* dT = ddT[w];
    float dC, sc1, sc2 = 0.0f;
    {
        const int j = pa.x, k = pa.y;
        float4 A = boxs[w][j], B = boxs[w][k];
        float iw = fmaxf(fminf(A.z, B.z) - fmaxf(A.x, B.x), 0.0f);
        float ih = fmaxf(fminf(A.w, B.w) - fmaxf(A.y, B.y), 0.0f);
        float inter = iw * ih;
        float aa = fmaxf(A.z - A.x, 0.0f) * fmaxf(A.w - A.y, 0.0f);
        float ab = fmaxf(B.z - B.x, 0.0f) * fmaxf(B.w - B.y, 0.0f);
        float d = 1.0f - __fdividef(inter, aa + ab - inter + 1e-12f);
        float yr = aw[j] * aw[k];          // (4a)(4a) = 16*rel
        float yd = d * 16.0f;
        float wgt = (j == k) ? 1.0f : 2.0f;
        float4 pr = tabRel[(int)yr];
        int id = (int)yd;
        float4 pd = tabDist[id];
        float2 p6 = tab6[id];
        sc1 = wgt * fmaf(yr, pr.y, pr.x) * fmaf(yd, pd.y, pd.x);
        float dd = fmaf(yr, pr.w, pr.z) * fmaf(yd, pd.w, pd.z);
        dT[j * STR + k] = dd;
        dT[k * STR + j] = dd;
        dC = wgt * fabsf(fmaf(yd, p6.y, p6.x) - 0.5f);
    }
    if (l < 23) {
        const int j = pa.z, k = pa.w;
        float4 A = boxs[w][j], B = boxs[w][k];
        float iw = fmaxf(fminf(A.z, B.z) - fmaxf(A.x, B.x), 0.0f);
        float ih = fmaxf(fminf(A.w, B.w) - fmaxf(A.y, B.y), 0.0f);
        float inter = iw * ih;
        float aa = fmaxf(A.z - A.x, 0.0f) * fmaxf(A.w - A.y, 0.0f);
        float ab = fmaxf(B.z - B.x, 0.0f) * fmaxf(B.w - B.y, 0.0f);
        float d = 1.0f - __fdividef(inter, aa + ab - inter + 1e-12f);
        float yr = aw[j] * aw[k];
        float yd = d * 16.0f;
        float wgt = (j == k) ? 1.0f : 2.0f;
        float4 pr = tabRel[(int)yr];
        int id = (int)yd;
        float4 pd = tabDist[id];
        float2 p6 = tab6[id];
        sc2 = wgt * fmaf(yr, pr.y, pr.x) * fmaf(yd, pd.y, pd.x);
        float dd = fmaf(yr, pr.w, pr.z) * fmaf(yd, pd.w, pd.z);
        dT[j * STR + k] = dd;
        dT[k * STR + j] = dd;
        dC += wgt * fabsf(fmaf(yd, p6.y, p6.x) - 0.5f);
    }
    __syncwarp();

    // ---- sim block1: pairs 0..31, full 11-term simprod per lane ----
    const uchar4 pb = g_pairB[l];
    float* sP = smP[w];
    {
        float prod = simprod(dT, tab2, pb.x, pb.y, aw[pb.x], aw[pb.y]);
        sP[pb.x * STR + pb.y] = prod;
        sP[pb.y * STR + pb.x] = prod;
    }
    // ---- sim block2: pairs 32..44, each split across 2 lanes (lanes 0-25) ----
    if (l < 26) {
        const int j = pb.z, k = pb.w, h = l & 1;
        const int off = h ? 4 : 0;
        // h=0: terms i0-3 + att + dummy plin(16)=csum[16]~=1; h=1: terms i4-9
        float4 cj = *(const float4*)(dT + j * STR + off);
        float4 ck = *(const float4*)(dT + k * STR + off);
        float2 ej = *(const float2*)(dT + j * STR + 8);
        float2 ek = *(const float2*)(dT + k * STR + 8);
        float t0 = plin2(tab2, fmaf(fabsf(cj.x - ck.x), -16.0f, 16.0f));
        float t1 = plin2(tab2, fmaf(fabsf(cj.y - ck.y), -16.0f, 16.0f));
        float t2 = plin2(tab2, fmaf(fabsf(cj.z - ck.z), -16.0f, 16.0f));
        float t3 = plin2(tab2, fmaf(fabsf(cj.w - ck.w), -16.0f, 16.0f));
        float a4 = h ? fmaf(fabsf(ej.x - ek.x), -16.0f, 16.0f)
                     : fmaf(fabsf(aw[j] - aw[k]), -4.0f, 16.0f);
        float a5 = h ? fmaf(fabsf(ej.y - ek.y), -16.0f, 16.0f) : 16.0f;
        float t4 = plin2(tab2, a4);
        float t5 = plin2(tab2, a5);
        float prod = ((t0 * t1) * (t2 * t3)) * (t4 * t5);
        prod *= __shfl_xor_sync(0x03FFFFFFu, prod, 1);
        if (h == 0) { sP[j * STR + k] = prod; sP[k * STR + j] = prod; }
    } else {
        sP[(l - 26) * (STR + 1)] = 1.0f;   // diagonals 0-5 (product == 1 exactly)
    }
    if (l < 4) sP[(l + 6) * (STR + 1)] = 1.0f;   // diagonals 6-9
    __syncwarp();

    // ---- row_sims reciprocal (lanes 0-9, vectorized) ----
    if (l < OBJ) {
        const float4* rp = (const float4*)(sP + l * STR);
        float4 x0 = rp[0], x1 = rp[1];
        float2 x2 = *(const float2*)(sP + l * STR + 8);
        float s = ((x0.x + x0.y) + (x0.z + x0.w)) + ((x1.x + x1.y) + (x1.z + x1.w)) + (x2.x + x2.y);
        invr[w][l] = __fdividef(1.0f, s);
    }
    __syncwarp();

    // ---- partials: scores / (rj*rk); correction + confs ----
    const float* ivw = invr[w];
    float sT = sc1 * ivw[pa.x] * ivw[pa.y];
    if (l < 23) sT += sc2 * ivw[pa.z] * ivw[pa.w];
    float mC = 0.01f * dC;
    if (l < OBJ) {
        float a4 = aw[l];
        float ya = a4 * a4;                        // 16 * a^2
        float4 pr = tabRel[(int)ya];
        sT += fmaf(ya, pr.y, pr.x) * ivw[l];
        mC += 0.1f * fabsf(plin2(tab5, a4 * 4.0f) - 0.5f);
    }

    // ---- butterfly reduction ----
    #pragma unroll
    for (int o = 16; o > 0; o >>= 1) {
        sT += __shfl_xor_sync(0xffffffffu, sT, o);
        mC += __shfl_xor_sync(0xffffffffu, mC, o);
    }
    float total = sqrtf(sT + 1e-20f);
    float conf  = plin2(tab7, mC * 16.0f);

    // ---- one_hot * conf, lanes 0-10 ----
    if (act && l < OBJ + 1) {
        float s = fminf(fmaxf(total, 0.0f), (float)OBJ);
        int i = (int)s;
        float f = s - truncf(s);
        int il = i < OBJ ? i : OBJ;
        int ir = (i + 1) < OBJ ? (i + 1) : OBJ;
        float v = (1.0f - f) * (l == il ? 1.0f : 0.0f) + f * (l == ir ? 1.0f : 0.0f);
        out[(size_t)row * (OBJ + 1) + l] = v * conf;
    }
}

extern "C" void kernel_launch(void* const* d_in, const int* in_sizes, int n_in,
                              void* d_out, int out_size) {
    const float* boxes     = (const float*)d_in[0];
    const float* attention = (const float*)d_in[1];
    const float* ws        = (const float*)d_in[2];
    float* out = (float*)d_out;
    int n = in_sizes[1] / MOBJ;
    counter_kernel<<<(n + RPB - 1) / RPB, 512>>>(boxes, attention, ws, out, n);
}

// round 13
// speedup vs baseline: 1.0732x; 1.0732x over previous
#include <cuda_runtime.h>
#include <cuda_bf16.h>
#include <math.h>

#define N_PL 16
#define OBJ  10
#define MOBJ 36
#define RPB  8     // rows (warps) per block
#define STR  12    // padded row stride for 10x10 matrices (48B, 16B-aligned)

// Compile-time pair tables (static .global data; coalesced 128B LDG per warp).
__device__ const uchar4 g_pairA[32] = {
    {0,0,3,8},{0,1,3,9},{0,2,4,4},{0,3,4,5},{0,4,4,6},{0,5,4,7},{0,6,4,8},{0,7,4,9},
    {0,8,5,5},{0,9,5,6},{1,1,5,7},{1,2,5,8},{1,3,5,9},{1,4,6,6},{1,5,6,7},{1,6,6,8},
    {1,7,6,9},{1,8,7,7},{1,9,7,8},{2,2,7,9},{2,3,8,8},{2,4,8,9},{2,5,9,9},{2,6,9,9},
    {2,7,9,9},{2,8,9,9},{2,9,9,9},{3,3,9,9},{3,4,9,9},{3,5,9,9},{3,6,9,9},{3,7,9,9}};
__device__ const uchar4 g_pairB[32] = {
    {0,1,4,7},{0,2,4,8},{0,3,4,9},{0,4,5,6},{0,5,5,7},{0,6,5,8},{0,7,5,9},{0,8,6,7},
    {0,9,6,8},{1,2,6,9},{1,3,7,8},{1,4,7,9},{1,5,8,9},{1,6,8,9},{1,7,8,9},{1,8,8,9},
    {1,9,8,9},{2,3,8,9},{2,4,8,9},{2,5,8,9},{2,6,8,9},{2,7,8,9},{2,8,8,9},{2,9,8,9},
    {3,4,8,9},{3,5,8,9},{3,6,8,9},{3,7,8,9},{3,8,8,9},{3,9,8,9},{4,5,8,9},{4,6,8,9}};

// plin on pre-scaled argument y = 16*x, y in [0,16]; plin = A[i] + y*B[i], i=(int)y
__device__ __forceinline__ float plin2(const float2* __restrict__ tb, float y) {
    int i = (int)y;
    float2 p = tb[i];
    return fmaf(y, p.y, p.x);
}

// product of 10 plin(1-|colj[i]-colk[i]|) + att term, vectorized loads + tree
__device__ __forceinline__ float simprod(const float* __restrict__ ddT,
                                         const float2* __restrict__ tb2,
                                         int j, int k, float a4j, float a4k) {
    const float4* cj = (const float4*)(ddT + j * STR);
    const float4* ck = (const float4*)(ddT + k * STR);
    float4 a0 = cj[0], b0 = ck[0];
    float4 a1 = cj[1], b1 = ck[1];
    float2 a2 = *(const float2*)(ddT + j * STR + 8);
    float2 b2 = *(const float2*)(ddT + k * STR + 8);
    float t0 = plin2(tb2, fmaf(fabsf(a0.x - b0.x), -16.0f, 16.0f));
    float t1 = plin2(tb2, fmaf(fabsf(a0.y - b0.y), -16.0f, 16.0f));
    float t2 = plin2(tb2, fmaf(fabsf(a0.z - b0.z), -16.0f, 16.0f));
    float t3 = plin2(tb2, fmaf(fabsf(a0.w - b0.w), -16.0f, 16.0f));
    float t4 = plin2(tb2, fmaf(fabsf(a1.x - b1.x), -16.0f, 16.0f));
    float t5 = plin2(tb2, fmaf(fabsf(a1.y - b1.y), -16.0f, 16.0f));
    float t6 = plin2(tb2, fmaf(fabsf(a1.z - b1.z), -16.0f, 16.0f));
    float t7 = plin2(tb2, fmaf(fabsf(a1.w - b1.w), -16.0f, 16.0f));
    float t8 = plin2(tb2, fmaf(fabsf(a2.x - b2.x), -16.0f, 16.0f));
    float t9 = plin2(tb2, fmaf(fabsf(a2.y - b2.y), -16.0f, 16.0f));
    float ta = plin2(tb2, fmaf(fabsf(a4j - a4k), -4.0f, 16.0f));   // att stored x4
    float p0 = (t0 * t1) * (t2 * t3);
    float p1 = (t4 * t5) * (t6 * t7);
    float p2 = (t8 * t9) * ta;
    return (p0 * p1) * p2;
}

__global__ __launch_bounds__(256, 6)
void counter_kernel(const float* __restrict__ boxes,      // [n, 4, 36]
                    const float* __restrict__ attention,  // [n, 36]
                    const float* __restrict__ ws,         // [8, 17]
                    float* __restrict__ out,              // [n, 11]
                    int n) {
    __shared__ float4 tabRel[N_PL + 1];    // (A0,B0,A3,B3) keyed by yr
    __shared__ float4 tabDist[N_PL + 1];   // (A1,B1,A4,B4) keyed by yd
    __shared__ float2 tab2[N_PL + 1];
    __shared__ float2 tab5[N_PL + 1];
    __shared__ float2 tab6[N_PL + 1];      // keyed by yd (index reused)
    __shared__ float2 tab7[N_PL + 1];
    __shared__ uint4  karr[RPB][9];        // 36 sortable 32-bit keys per row
    __shared__ float  att[RPB][OBJ];       // holds 4*sigmoid
    __shared__ float4 boxs[RPB][OBJ];
    __shared__ float  areaS[RPB][OBJ];     // precomputed box areas
    __shared__ float  ddT[RPB][OBJ * STR];
    __shared__ float  smP[RPB][OBJ * STR];
    __shared__ float  invr[RPB][OBJ];

    const int t = threadIdx.x;
    const int w = t >> 5, l = t & 31;
    const int row = blockIdx.x * RPB + w;
    const bool act = row < n;

    // ---- plin table w built by warp w: |ws|, shfl inclusive scan, normalize ----
    {
        float wv0 = (l <= N_PL) ? fabsf(ws[w * 17 + l]) : 0.0f;
        float cs = wv0;
        #pragma unroll
        for (int o = 1; o <= 16; o <<= 1) {
            float up = __shfl_up_sync(0xffffffffu, cs, o);
            if (l >= o) cs += up;
        }
        float totalw = __shfl_sync(0xffffffffu, cs, N_PL);
        float inv = __fdividef(1.0f, totalw);
        float wnext = __shfl_down_sync(0xffffffffu, wv0, 1);
        float B = (l < N_PL) ? wnext * inv : 0.0f;
        float A = fmaf(-(float)l, B, cs * inv);
        if (l <= N_PL) {
            if      (w == 0) { ((float*)tabRel)[4*l]   = A; ((float*)tabRel)[4*l+1]  = B; }
            else if (w == 3) { ((float*)tabRel)[4*l+2] = A; ((float*)tabRel)[4*l+3]  = B; }
            else if (w == 1) { ((float*)tabDist)[4*l]  = A; ((float*)tabDist)[4*l+1] = B; }
            else if (w == 4) { ((float*)tabDist)[4*l+2]= A; ((float*)tabDist)[4*l+3] = B; }
            else if (w == 2) tab2[l] = make_float2(A, B);
            else if (w == 5) tab5[l] = make_float2(A, B);
            else if (w == 6) tab6[l] = make_float2(A, B);
            else             tab7[l] = make_float2(A, B);
        }
    }

    // ---- load attention, build monotone 32-bit sortable keys (branchless) ----
    float v1 = 0.0f, v2 = 0.0f;
    if (act) {
        v1 = attention[(size_t)row * MOBJ + l];
        if (l < 4) v2 = attention[(size_t)row * MOBJ + 32 + l];
    }
    unsigned u1 = __float_as_uint(v1);
    unsigned kv1 = u1 ^ (unsigned)(((int)u1 >> 31) | 0x80000000);
    ((unsigned*)karr[w])[l] = kv1;
    unsigned u2 = __float_as_uint(v2);
    unsigned kv2 = u2 ^ (unsigned)(((int)u2 >> 31) | 0x80000000);
    if (l < 4) ((unsigned*)karr[w])[32 + l] = kv2;
    __syncthreads();   // the ONLY block barrier: tables (cross-warp) + own keys

    // ---- rank among all 36 via strict > (keys unique: continuous input data) ----
    int r1 = 0;
    const uint4* kp = karr[w];
    #pragma unroll
    for (int p = 0; p < 9; p++) {
        uint4 kk = kp[p];
        r1 += (kk.x > kv1) + (kk.y > kv1) + (kk.z > kv1) + (kk.w > kv1);
    }
    uint4 ex = kp[8];   // keys 32..35

    unsigned b0 = __ballot_sync(0xffffffffu, kv1 > ex.x);
    unsigned b1 = __ballot_sync(0xffffffffu, kv1 > ex.y);
    unsigned b2 = __ballot_sync(0xffffffffu, kv1 > ex.z);
    unsigned b3 = __ballot_sync(0xffffffffu, kv1 > ex.w);
    int r2 = (l == 0) ? __popc(b0) : (l == 1) ? __popc(b1) : (l == 2) ? __popc(b2) : __popc(b3);
    r2 += (ex.x > kv2) + (ex.y > kv2) + (ex.z > kv2) + (ex.w > kv2);

    // ---- gather selected objects (att stored as 4*sigmoid; areas precomputed) ----
    if (act && r1 < OBJ) {
        att[w][r1] = __fdividef(4.0f, 1.0f + __expf(-v1));
        const float* bp = boxes + (size_t)row * (4 * MOBJ) + l;
        float4 b4 = make_float4(bp[0], bp[MOBJ], bp[2 * MOBJ], bp[3 * MOBJ]);
        boxs[w][r1] = b4;
        areaS[w][r1] = fmaxf(b4.z - b4.x, 0.0f) * fmaxf(b4.w - b4.y, 0.0f);
    }
    if (act && l < 4 && r2 < OBJ) {
        att[w][r2] = __fdividef(4.0f, 1.0f + __expf(-v2));
        const float* bp = boxes + (size_t)row * (4 * MOBJ) + 32 + l;
        float4 b4 = make_float4(bp[0], bp[MOBJ], bp[2 * MOBJ], bp[3 * MOBJ]);
        boxs[w][r2] = b4;
        areaS[w][r2] = fmaxf(b4.z - b4.x, 0.0f) * fmaxf(b4.w - b4.y, 0.0f);
    }
    __syncwarp();

    // ---- pairwise (55 pairs: lane l; lanes 0-22 also pair 32+l) ----
    const uchar4 pa = g_pairA[l];
    const float* aw = att[w];
    const float* arw = areaS[w];
    float* dT = ddT[w];
    float dC, sc1, sc2 = 0.0f;
    {
        const int j = pa.x, k = pa.y;
        float4 A = boxs[w][j], B = boxs[w][k];
        float iw = fmaxf(fminf(A.z, B.z) - fmaxf(A.x, B.x), 0.0f);
        float ih = fmaxf(fminf(A.w, B.w) - fmaxf(A.y, B.y), 0.0f);
        float inter = iw * ih;
        float d = 1.0f - __fdividef(inter, arw[j] + arw[k] - inter + 1e-12f);
        float yr = aw[j] * aw[k];          // (4a)(4a) = 16*rel
        float yd = d * 16.0f;
        float wgt = (j == k) ? 1.0f : 2.0f;
        float4 pr = tabRel[(int)yr];
        int id = (int)yd;
        float4 pd = tabDist[id];
        float2 p6 = tab6[id];
        sc1 = wgt * fmaf(yr, pr.y, pr.x) * fmaf(yd, pd.y, pd.x);
        float dd = fmaf(yr, pr.w, pr.z) * fmaf(yd, pd.w, pd.z);
        dT[j * STR + k] = dd;
        dT[k * STR + j] = dd;
        dC = wgt * fabsf(fmaf(yd, p6.y, p6.x) - 0.5f);
    }
    if (l < 23) {
        const int j = pa.z, k = pa.w;
        float4 A = boxs[w][j], B = boxs[w][k];
        float iw = fmaxf(fminf(A.z, B.z) - fmaxf(A.x, B.x), 0.0f);
        float ih = fmaxf(fminf(A.w, B.w) - fmaxf(A.y, B.y), 0.0f);
        float inter = iw * ih;
        float d = 1.0f - __fdividef(inter, arw[j] + arw[k] - inter + 1e-12f);
        float yr = aw[j] * aw[k];
        float yd = d * 16.0f;
        float wgt = (j == k) ? 1.0f : 2.0f;
        float4 pr = tabRel[(int)yr];
        int id = (int)yd;
        float4 pd = tabDist[id];
        float2 p6 = tab6[id];
        sc2 = wgt * fmaf(yr, pr.y, pr.x) * fmaf(yd, pd.y, pd.x);
        float dd = fmaf(yr, pr.w, pr.z) * fmaf(yd, pd.w, pd.z);
        dT[j * STR + k] = dd;
        dT[k * STR + j] = dd;
        dC += wgt * fabsf(fmaf(yd, p6.y, p6.x) - 0.5f);
    }
    __syncwarp();

    // ---- sim (45 strict pairs: lane l; lanes 0-12 also 32+l; lanes 22-31 diag) ----
    const uchar4 pb = g_pairB[l];
    float* sP = smP[w];
    {
        float prod = simprod(dT, tab2, pb.x, pb.y, aw[pb.x], aw[pb.y]);
        sP[pb.x * STR + pb.y] = prod;
        sP[pb.y * STR + pb.x] = prod;
    }
    if (l < 13) {
        float prod = simprod(dT, tab2, pb.z, pb.w, aw[pb.z], aw[pb.w]);
        sP[pb.z * STR + pb.w] = prod;
        sP[pb.w * STR + pb.z] = prod;
    } else if (l >= 22) {
        sP[(l - 22) * (STR + 1)] = 1.0f;   // diagonal product == 1 (diffs identically 0)
    }
    __syncwarp();

    // ---- row_sims reciprocal (lanes 0-9, vectorized) ----
    if (l < OBJ) {
        const float4* rp = (const float4*)(sP + l * STR);
        float4 x0 = rp[0], x1 = rp[1];
        float2 x2 = *(const float2*)(sP + l * STR + 8);
        float s = ((x0.x + x0.y) + (x0.z + x0.w)) + ((x1.x + x1.y) + (x1.z + x1.w)) + (x2.x + x2.y);
        invr[w][l] = __fdividef(1.0f, s);
    }
    __syncwarp();

    // ---- partials: scores / (rj*rk); correction + confs ----
    const float* ivw = invr[w];
    float sT = sc1 * ivw[pa.x] * ivw[pa.y];
    if (l < 23) sT += sc2 * ivw[pa.z] * ivw[pa.w];
    float mC = 0.01f * dC;
    if (l < OBJ) {
        float a4 = aw[l];
        float ya = a4 * a4;                        // 16 * a^2
        float4 pr = tabRel[(int)ya];
        sT += fmaf(ya, pr.y, pr.x) * ivw[l];
        mC += 0.1f * fabsf(plin2(tab5, a4 * 4.0f) - 0.5f);
    }

    // ---- butterfly reduction ----
    #pragma unroll
    for (int o = 16; o > 0; o >>= 1) {
        sT += __shfl_xor_sync(0xffffffffu, sT, o);
        mC += __shfl_xor_sync(0xffffffffu, mC, o);
    }
    float total = sqrtf(sT + 1e-20f);
    float conf  = plin2(tab7, mC * 16.0f);

    // ---- one_hot * conf, lanes 0-10 (select chain; exact when il==ir since f=0) ----
    if (act && l < OBJ + 1) {
        float s = fminf(fmaxf(total, 0.0f), (float)OBJ);
        int i = (int)s;
        float f = s - truncf(s);
        int il = i < OBJ ? i : OBJ;
        int ir = (i + 1) < OBJ ? (i + 1) : OBJ;
        float v = (l == il) ? (1.0f - f) : ((l == ir) ? f : 0.0f);
        out[(size_t)row * (OBJ + 1) + l] = v * conf;
    }
}

extern "C" void kernel_launch(void* const* d_in, const int* in_sizes, int n_in,
                              void* d_out, int out_size) {
    const float* boxes     = (const float*)d_in[0];
    const float* attention = (const float*)d_in[1];
    const float* ws        = (const float*)d_in[2];
    float* out = (float*)d_out;
    int n = in_sizes[1] / MOBJ;
    counter_kernel<<<(n + RPB - 1) / RPB, 256>>>(boxes, attention, ws, out, n);
}

// round 14
// speedup vs baseline: 1.0842x; 1.0103x over previous
#include <cuda_runtime.h>
#include <cuda_bf16.h>
#include <math.h>

#define N_PL 16
#define OBJ  10
#define MOBJ 36
#define RPB  8     // rows (warps) per block
#define STR  12    // padded row stride for 10x10 matrices (48B, 16B-aligned)

// Compile-time pair tables (static .global data; coalesced 128B LDG per warp).
__device__ const uchar4 g_pairA[32] = {
    {0,0,3,8},{0,1,3,9},{0,2,4,4},{0,3,4,5},{0,4,4,6},{0,5,4,7},{0,6,4,8},{0,7,4,9},
    {0,8,5,5},{0,9,5,6},{1,1,5,7},{1,2,5,8},{1,3,5,9},{1,4,6,6},{1,5,6,7},{1,6,6,8},
    {1,7,6,9},{1,8,7,7},{1,9,7,8},{2,2,7,9},{2,3,8,8},{2,4,8,9},{2,5,9,9},{2,6,9,9},
    {2,7,9,9},{2,8,9,9},{2,9,9,9},{3,3,9,9},{3,4,9,9},{3,5,9,9},{3,6,9,9},{3,7,9,9}};
__device__ const uchar4 g_pairB[32] = {
    {0,1,4,7},{0,2,4,8},{0,3,4,9},{0,4,5,6},{0,5,5,7},{0,6,5,8},{0,7,5,9},{0,8,6,7},
    {0,9,6,8},{1,2,6,9},{1,3,7,8},{1,4,7,9},{1,5,8,9},{1,6,8,9},{1,7,8,9},{1,8,8,9},
    {1,9,8,9},{2,3,8,9},{2,4,8,9},{2,5,8,9},{2,6,8,9},{2,7,8,9},{2,8,8,9},{2,9,8,9},
    {3,4,8,9},{3,5,8,9},{3,6,8,9},{3,7,8,9},{3,8,8,9},{3,9,8,9},{4,5,8,9},{4,6,8,9}};

// plin on pre-scaled argument y = 16*x, y in [0,16]; plin = A[i] + y*B[i], i=(int)y
__device__ __forceinline__ float plin2(const float2* __restrict__ tb, float y) {
    int i = (int)y;
    float2 p = tb[i];
    return fmaf(y, p.y, p.x);
}

// product of 10 plin(1-|colj[i]-colk[i]|) + att term, vectorized loads + tree
__device__ __forceinline__ float simprod(const float* __restrict__ ddT,
                                         const float2* __restrict__ tb2,
                                         int j, int k, float a4j, float a4k) {
    const float4* cj = (const float4*)(ddT + j * STR);
    const float4* ck = (const float4*)(ddT + k * STR);
    float4 a0 = cj[0], b0 = ck[0];
    float4 a1 = cj[1], b1 = ck[1];
    float2 a2 = *(const float2*)(ddT + j * STR + 8);
    float2 b2 = *(const float2*)(ddT + k * STR + 8);
    float t0 = plin2(tb2, fmaf(fabsf(a0.x - b0.x), -16.0f, 16.0f));
    float t1 = plin2(tb2, fmaf(fabsf(a0.y - b0.y), -16.0f, 16.0f));
    float t2 = plin2(tb2, fmaf(fabsf(a0.z - b0.z), -16.0f, 16.0f));
    float t3 = plin2(tb2, fmaf(fabsf(a0.w - b0.w), -16.0f, 16.0f));
    float t4 = plin2(tb2, fmaf(fabsf(a1.x - b1.x), -16.0f, 16.0f));
    float t5 = plin2(tb2, fmaf(fabsf(a1.y - b1.y), -16.0f, 16.0f));
    float t6 = plin2(tb2, fmaf(fabsf(a1.z - b1.z), -16.0f, 16.0f));
    float t7 = plin2(tb2, fmaf(fabsf(a1.w - b1.w), -16.0f, 16.0f));
    float t8 = plin2(tb2, fmaf(fabsf(a2.x - b2.x), -16.0f, 16.0f));
    float t9 = plin2(tb2, fmaf(fabsf(a2.y - b2.y), -16.0f, 16.0f));
    float ta = plin2(tb2, fmaf(fabsf(a4j - a4k), -4.0f, 16.0f));   // att stored x4
    float p0 = (t0 * t1) * (t2 * t3);
    float p1 = (t4 * t5) * (t6 * t7);
    float p2 = (t8 * t9) * ta;
    return (p0 * p1) * p2;
}

__global__ __launch_bounds__(256, 7)
void counter_kernel(const float* __restrict__ boxes,      // [n, 4, 36]
                    const float* __restrict__ attention,  // [n, 36]
                    const float* __restrict__ ws,         // [8, 17]
                    float* __restrict__ out,              // [n, 11]
                    int n) {
    __shared__ float4 tabRel[N_PL + 1];    // (A0,B0,A3,B3) keyed by yr
    __shared__ float4 tabDist[N_PL + 1];   // (A1,B1,A4,B4) keyed by yd
    __shared__ float2 tab2[N_PL + 1];
    __shared__ float2 tab5[N_PL + 1];
    __shared__ float2 tab6[N_PL + 1];      // keyed by yd (index reused)
    __shared__ float2 tab7[N_PL + 1];
    __shared__ uint4  karr[RPB][9];        // 36 sortable 32-bit keys per row
    __shared__ float  att[RPB][OBJ];       // holds 4*sigmoid
    __shared__ float4 boxs[RPB][OBJ];
    __shared__ float  areaS[RPB][OBJ];     // precomputed box areas
    __shared__ float  ddT[RPB][OBJ * STR];
    __shared__ float  smP[RPB][OBJ * STR];
    __shared__ float  invr[RPB][OBJ];

    const int t = threadIdx.x;
    const int w = t >> 5, l = t & 31;
    const int row = blockIdx.x * RPB + w;
    const bool act = row < n;

    // ---- plin table w built by warp w: |ws|, shfl inclusive scan, normalize ----
    {
        float wv0 = (l <= N_PL) ? fabsf(ws[w * 17 + l]) : 0.0f;
        float cs = wv0;
        #pragma unroll
        for (int o = 1; o <= 16; o <<= 1) {
            float up = __shfl_up_sync(0xffffffffu, cs, o);
            if (l >= o) cs += up;
        }
        float totalw = __shfl_sync(0xffffffffu, cs, N_PL);
        float inv = __fdividef(1.0f, totalw);
        float wnext = __shfl_down_sync(0xffffffffu, wv0, 1);
        float B = (l < N_PL) ? wnext * inv : 0.0f;
        float A = fmaf(-(float)l, B, cs * inv);
        if (l <= N_PL) {
            if      (w == 0) { ((float*)tabRel)[4*l]   = A; ((float*)tabRel)[4*l+1]  = B; }
            else if (w == 3) { ((float*)tabRel)[4*l+2] = A; ((float*)tabRel)[4*l+3]  = B; }
            else if (w == 1) { ((float*)tabDist)[4*l]  = A; ((float*)tabDist)[4*l+1] = B; }
            else if (w == 4) { ((float*)tabDist)[4*l+2]= A; ((float*)tabDist)[4*l+3] = B; }
            else if (w == 2) tab2[l] = make_float2(A, B);
            else if (w == 5) tab5[l] = make_float2(A, B);
            else if (w == 6) tab6[l] = make_float2(A, B);
            else             tab7[l] = make_float2(A, B);
        }
    }

    // ---- load attention, build monotone 32-bit sortable keys (branchless) ----
    float v1 = 0.0f, v2 = 0.0f;
    if (act) {
        v1 = attention[(size_t)row * MOBJ + l];
        if (l < 4) v2 = attention[(size_t)row * MOBJ + 32 + l];
    }
    unsigned u1 = __float_as_uint(v1);
    unsigned kv1 = u1 ^ (unsigned)(((int)u1 >> 31) | 0x80000000);
    ((unsigned*)karr[w])[l] = kv1;
    unsigned u2 = __float_as_uint(v2);
    unsigned kv2 = u2 ^ (unsigned)(((int)u2 >> 31) | 0x80000000);
    if (l < 4) ((unsigned*)karr[w])[32 + l] = kv2;
    __syncthreads();   // the ONLY block barrier: tables (cross-warp) + own keys

    // ---- rank among all 36 via strict > (keys unique: continuous input data) ----
    int r1 = 0;
    const uint4* kp = karr[w];
    #pragma unroll
    for (int p = 0; p < 9; p++) {
        uint4 kk = kp[p];
        r1 += (kk.x > kv1) + (kk.y > kv1) + (kk.z > kv1) + (kk.w > kv1);
    }
    uint4 ex = kp[8];   // keys 32..35

    unsigned b0 = __ballot_sync(0xffffffffu, kv1 > ex.x);
    unsigned b1 = __ballot_sync(0xffffffffu, kv1 > ex.y);
    unsigned b2 = __ballot_sync(0xffffffffu, kv1 > ex.z);
    unsigned b3 = __ballot_sync(0xffffffffu, kv1 > ex.w);
    int r2 = (l == 0) ? __popc(b0) : (l == 1) ? __popc(b1) : (l == 2) ? __popc(b2) : __popc(b3);
    r2 += (ex.x > kv2) + (ex.y > kv2) + (ex.z > kv2) + (ex.w > kv2);

    // ---- gather selected objects (att stored as 4*sigmoid; areas precomputed) ----
    if (act && r1 < OBJ) {
        att[w][r1] = __fdividef(4.0f, 1.0f + __expf(-v1));
        const float* bp = boxes + (size_t)row * (4 * MOBJ) + l;
        float4 b4 = make_float4(bp[0], bp[MOBJ], bp[2 * MOBJ], bp[3 * MOBJ]);
        boxs[w][r1] = b4;
        areaS[w][r1] = fmaxf(b4.z - b4.x, 0.0f) * fmaxf(b4.w - b4.y, 0.0f);
    }
    if (act && l < 4 && r2 < OBJ) {
        att[w][r2] = __fdividef(4.0f, 1.0f + __expf(-v2));
        const float* bp = boxes + (size_t)row * (4 * MOBJ) + 32 + l;
        float4 b4 = make_float4(bp[0], bp[MOBJ], bp[2 * MOBJ], bp[3 * MOBJ]);
        boxs[w][r2] = b4;
        areaS[w][r2] = fmaxf(b4.z - b4.x, 0.0f) * fmaxf(b4.w - b4.y, 0.0f);
    }
    __syncwarp();

    // ---- pairwise (55 pairs: lane l; lanes 0-22 also pair 32+l) ----
    const uchar4 pa = g_pairA[l];
    const float* aw = att[w];
    const float* arw = areaS[w];
    float* dT = ddT[w];
    float dC, sc1, sc2 = 0.0f;
    {
        const int j = pa.x, k = pa.y;
        float4 A = boxs[w][j], B = boxs[w][k];
        float iw = fmaxf(fminf(A.z, B.z) - fmaxf(A.x, B.x), 0.0f);
        float ih = fmaxf(fminf(A.w, B.w) - fmaxf(A.y, B.y), 0.0f);
        float inter = iw * ih;
        float d = 1.0f - __fdividef(inter, arw[j] + arw[k] - inter + 1e-12f);
        float yr = aw[j] * aw[k];          // (4a)(4a) = 16*rel
        float yd = d * 16.0f;
        float wgt = (j == k) ? 1.0f : 2.0f;
        float4 pr = tabRel[(int)yr];
        int id = (int)yd;
        float4 pd = tabDist[id];
        float2 p6 = tab6[id];
        sc1 = wgt * fmaf(yr, pr.y, pr.x) * fmaf(yd, pd.y, pd.x);
        float dd = fmaf(yr, pr.w, pr.z) * fmaf(yd, pd.w, pd.z);
        dT[j * STR + k] = dd;
        dT[k * STR + j] = dd;
        dC = wgt * fabsf(fmaf(yd, p6.y, p6.x) - 0.5f);
    }
    if (l < 23) {
        const int j = pa.z, k = pa.w;
        float4 A = boxs[w][j], B = boxs[w][k];
        float iw = fmaxf(fminf(A.z, B.z) - fmaxf(A.x, B.x), 0.0f);
        float ih = fmaxf(fminf(A.w, B.w) - fmaxf(A.y, B.y), 0.0f);
        float inter = iw * ih;
        float d = 1.0f - __fdividef(inter, arw[j] + arw[k] - inter + 1e-12f);
        float yr = aw[j] * aw[k];
        float yd = d * 16.0f;
        float wgt = (j == k) ? 1.0f : 2.0f;
        float4 pr = tabRel[(int)yr];
        int id = (int)yd;
        float4 pd = tabDist[id];
        float2 p6 = tab6[id];
        sc2 = wgt * fmaf(yr, pr.y, pr.x) * fmaf(yd, pd.y, pd.x);
        float dd = fmaf(yr, pr.w, pr.z) * fmaf(yd, pd.w, pd.z);
        dT[j * STR + k] = dd;
        dT[k * STR + j] = dd;
        dC += wgt * fabsf(fmaf(yd, p6.y, p6.x) - 0.5f);
    }
    __syncwarp();

    // ---- sim (45 strict pairs: lane l; lanes 0-12 also 32+l; lanes 22-31 diag) ----
    const uchar4 pb = g_pairB[l];
    float* sP = smP[w];
    {
        float prod = simprod(dT, tab2, pb.x, pb.y, aw[pb.x], aw[pb.y]);
        sP[pb.x * STR + pb.y] = prod;
        sP[pb.y * STR + pb.x] = prod;
    }
    if (l < 13) {
        float prod = simprod(dT, tab2, pb.z, pb.w, aw[pb.z], aw[pb.w]);
        sP[pb.z * STR + pb.w] = prod;
        sP[pb.w * STR + pb.z] = prod;
    } else if (l >= 22) {
        sP[(l - 22) * (STR + 1)] = 1.0f;   // diagonal product == 1 (diffs identically 0)
    }
    __syncwarp();

    // ---- row_sims reciprocal (lanes 0-9, vectorized) ----
    if (l < OBJ) {
        const float4* rp = (const float4*)(sP + l * STR);
        float4 x0 = rp[0], x1 = rp[1];
        float2 x2 = *(const float2*)(sP + l * STR + 8);
        float s = ((x0.x + x0.y) + (x0.z + x0.w)) + ((x1.x + x1.y) + (x1.z + x1.w)) + (x2.x + x2.y);
        invr[w][l] = __fdividef(1.0f, s);
    }
    __syncwarp();

    // ---- partials: scores / (rj*rk); correction + confs ----
    const float* ivw = invr[w];
    float sT = sc1 * ivw[pa.x] * ivw[pa.y];
    if (l < 23) sT += sc2 * ivw[pa.z] * ivw[pa.w];
    float mC = 0.01f * dC;
    if (l < OBJ) {
        float a4 = aw[l];
        float ya = a4 * a4;                        // 16 * a^2
        float4 pr = tabRel[(int)ya];
        sT += fmaf(ya, pr.y, pr.x) * ivw[l];
        mC += 0.1f * fabsf(plin2(tab5, a4 * 4.0f) - 0.5f);
    }

    // ---- butterfly reduction ----
    #pragma unroll
    for (int o = 16; o > 0; o >>= 1) {
        sT += __shfl_xor_sync(0xffffffffu, sT, o);
        mC += __shfl_xor_sync(0xffffffffu, mC, o);
    }
    float total = sqrtf(sT + 1e-20f);
    float conf  = plin2(tab7, mC * 16.0f);

    // ---- one_hot * conf, lanes 0-10 (select chain; exact when il==ir since f=0) ----
    if (act && l < OBJ + 1) {
        float s = fminf(fmaxf(total, 0.0f), (float)OBJ);
        int i = (int)s;
        float f = s - truncf(s);
        int il = i < OBJ ? i : OBJ;
        int ir = (i + 1) < OBJ ? (i + 1) : OBJ;
        float v = (l == il) ? (1.0f - f) : ((l == ir) ? f : 0.0f);
        out[(size_t)row * (OBJ + 1) + l] = v * conf;
    }
}

extern "C" void kernel_launch(void* const* d_in, const int* in_sizes, int n_in,
                              void* d_out, int out_size) {
    const float* boxes     = (const float*)d_in[0];
    const float* attention = (const float*)d_in[1];
    const float* ws        = (const float*)d_in[2];
    float* out = (float*)d_out;
    int n = in_sizes[1] / MOBJ;
    counter_kernel<<<(n + RPB - 1) / RPB, 256>>>(boxes, attention, ws, out, n);
}